// round 4
// baseline (speedup 1.0000x reference)
#include <cuda_runtime.h>

#define NROWS 8192
#define DIM   512
#define HID   1024

// Scratch (allocation-free: __device__ globals), all 16B-aligned.
__device__ __align__(16) float g_part[128 * DIM];
__device__ __align__(16) float g_s[DIM];
__device__ __align__(16) float g_a1[DIM], g_c1[DIM];
__device__ __align__(16) float g_a2[DIM], g_c2[DIM];
__device__ __align__(16) float g_y[(size_t)NROWS * HID];   // 32 MB

// ---------------- tf32 + mma helpers ----------------
__device__ __forceinline__ unsigned tf32r(float x) {
    unsigned r;
    asm("cvt.rna.tf32.f32 %0, %1;" : "=r"(r) : "f"(x));
    return r;
}
__device__ __forceinline__ void mma_tf32(float* d, const unsigned* a, const unsigned* b) {
    asm volatile(
        "mma.sync.aligned.m16n8k8.row.col.f32.tf32.tf32.f32 "
        "{%0,%1,%2,%3}, {%4,%5,%6,%7}, {%8,%9}, {%0,%1,%2,%3};"
        : "+f"(d[0]), "+f"(d[1]), "+f"(d[2]), "+f"(d[3])
        : "r"(a[0]), "r"(a[1]), "r"(a[2]), "r"(a[3]), "r"(b[0]), "r"(b[1]));
}

// ---------------- stage 1: column partial sums of h ----------------
__global__ void colsum_kernel(const float* __restrict__ h) {
    int d  = threadIdx.x;
    int r0 = blockIdx.x * 64;
    float s = 0.f;
#pragma unroll 8
    for (int r = 0; r < 64; r++)
        s += h[(size_t)(r0 + r) * DIM + d];
    g_part[blockIdx.x * DIM + d] = s;
}

// ---------------- stage 2: s = colsum(h)@vw + N*vb ----------------
__global__ void prep1_kernel(const float* __restrict__ vw,
                             const float* __restrict__ vb) {
    __shared__ float hs[DIM];
    for (int i = threadIdx.x; i < DIM; i += blockDim.x) {
        float s = 0.f;
#pragma unroll 8
        for (int b = 0; b < 128; b++) s += g_part[b * DIM + i];
        hs[i] = s;
    }
    __syncthreads();
    int d = blockIdx.x * blockDim.x + threadIdx.x;
    float s = 0.f;
#pragma unroll 8
    for (int k = 0; k < DIM; k++) s = fmaf(hs[k], vw[k * DIM + d], s);
    g_s[d] = s + 8192.0f * vb[d];
}

// ---------------- stage 3: t = s@ow+ob; fold bn affines ----------------
__global__ void prep2_kernel(const float* __restrict__ ow, const float* __restrict__ ob,
                             const float* __restrict__ g1, const float* __restrict__ b1,
                             const float* __restrict__ m1, const float* __restrict__ v1,
                             const float* __restrict__ g2, const float* __restrict__ b2,
                             const float* __restrict__ m2, const float* __restrict__ v2) {
    __shared__ float ss[DIM];
    for (int i = threadIdx.x; i < DIM; i += blockDim.x) ss[i] = g_s[i];
    __syncthreads();
    int d = blockIdx.x * blockDim.x + threadIdx.x;
    float t = 0.f;
#pragma unroll 8
    for (int k = 0; k < DIM; k++) t = fmaf(ss[k], ow[k * DIM + d], t);
    t += ob[d];
    float A1 = g1[d] * rsqrtf(v1[d] + 1e-5f);
    g_a1[d] = A1;
    g_c1[d] = (t - m1[d]) * A1 + b1[d];
    float A2 = g2[d] * rsqrtf(v2[d] + 1e-5f);
    g_a2[d] = A2;
    g_c2[d] = b2[d] - m2[d] * A2;
}

// =====================================================================
// Double-buffered tf32 MMA GEMMs. Block 128x128, BK=32, 8 warps (4x2),
// warp tile 32x64. SMEM fragment-order layout (as R3), ping-pong bufs.
// Dynamic smem: A[2][4096] u32 @ 0, B[2][4096] u32 @ 8192. 64 KB total.
// =====================================================================

// ---- staging macros (use local vars: bm, bn, arow0, ac4, bk0w, bn4) ----
#define STAGE_LOAD(pa, pb, Ap, ldA, Bp, ldB, k0)                              \
    _Pragma("unroll")                                                         \
    for (int i = 0; i < 4; i++)                                               \
        pa[i] = *(const float4*)(Ap + (size_t)(bm + arow0 + 32 * i) * ldA +   \
                                 (k0) + ac4);                                 \
    _Pragma("unroll")                                                         \
    for (int i = 0; i < 4; i++)                                               \
        pb[i] = *(const float4*)(Bp + (size_t)((k0) + bk0w + 8 * i) * ldB +   \
                                 bn + bn4);

#define STORE_A_AFF(dst, pa, k0)                                              \
    {                                                                         \
        const int kstep = ac4 >> 3;                                           \
        const int jhi = ((ac4 >> 2) & 1) << 1;                                \
        float4 av = *(const float4*)(g_a1 + (k0) + ac4);                      \
        float4 cv = *(const float4*)(g_c1 + (k0) + ac4);                      \
        _Pragma("unroll")                                                     \
        for (int i = 0; i < 4; i++) {                                         \
            int row = arow0 + 32 * i;                                         \
            int mtile = row >> 4, lane_r = (row & 7) << 2;                    \
            int j = jhi | ((row >> 3) & 1);                                   \
            float vals[4] = {fmaf(pa[i].x, av.x, cv.x),                       \
                             fmaf(pa[i].y, av.y, cv.y),                       \
                             fmaf(pa[i].z, av.z, cv.z),                       \
                             fmaf(pa[i].w, av.w, cv.w)};                      \
            unsigned* base = (dst) + ((kstep << 3) + mtile) * 128 + j;        \
            _Pragma("unroll")                                                 \
            for (int jj = 0; jj < 4; jj++)                                    \
                base[(((lane_r + jj + kstep) & 31) << 2)] = tf32r(vals[jj]);  \
        }                                                                     \
    }

#define STORE_A_PLAIN(dst, pa)                                                \
    {                                                                         \
        const int kstep = ac4 >> 3;                                           \
        const int jhi = ((ac4 >> 2) & 1) << 1;                                \
        _Pragma("unroll")                                                     \
        for (int i = 0; i < 4; i++) {                                         \
            int row = arow0 + 32 * i;                                         \
            int mtile = row >> 4, lane_r = (row & 7) << 2;                    \
            int j = jhi | ((row >> 3) & 1);                                   \
            float vals[4] = {pa[i].x, pa[i].y, pa[i].z, pa[i].w};             \
            unsigned* base = (dst) + ((kstep << 3) + mtile) * 128 + j;        \
            _Pragma("unroll")                                                 \
            for (int jj = 0; jj < 4; jj++)                                    \
                base[(((lane_r + jj + kstep) & 31) << 2)] = tf32r(vals[jj]);  \
        }                                                                     \
    }

#define STORE_B(dst, pb)                                                      \
    {                                                                         \
        const int jB = (bk0w >> 2) & 1;                                       \
        const int k3 = bk0w & 3;                                              \
        const int ntile = bn4 >> 3;                                           \
        const int lbase = (bn4 & 7) << 2;                                     \
        _Pragma("unroll")                                                     \
        for (int i = 0; i < 4; i++) {                                         \
            float vals[4] = {pb[i].x, pb[i].y, pb[i].z, pb[i].w};             \
            unsigned* base = (dst) + ((i << 4) + ntile) * 64 + jB;            \
            _Pragma("unroll")                                                 \
            for (int jj = 0; jj < 4; jj++) {                                  \
                int phys = ((lbase + (jj << 2)) | k3) + ntile;                \
                base[(phys & 31) << 1] = tf32r(vals[jj]);                     \
            }                                                                 \
        }                                                                     \
    }

#define COMPUTE_BLOCK(AsB, BsB)                                               \
    _Pragma("unroll")                                                         \
    for (int ks = 0; ks < 4; ks++) {                                          \
        unsigned afr0[4], afr1[4];                                            \
        int physa = (lane + ks) & 31;                                         \
        {                                                                     \
            uint4 v = *(const uint4*)&(AsB)[((ks << 3) + w_m * 2) * 128 +     \
                                            physa * 4];                       \
            afr0[0] = v.x; afr0[1] = v.y; afr0[2] = v.z; afr0[3] = v.w;       \
        }                                                                     \
        {                                                                     \
            uint4 v = *(const uint4*)&(AsB)[((ks << 3) + w_m * 2 + 1) * 128 + \
                                            physa * 4];                       \
            afr1[0] = v.x; afr1[1] = v.y; afr1[2] = v.z; afr1[3] = v.w;       \
        }                                                                     \
        unsigned bcur[2], bnxt[2];                                            \
        {                                                                     \
            int nt0 = w_n * 8;                                                \
            int pb_ = (lane + nt0) & 31;                                      \
            uint2 v = *(const uint2*)&(BsB)[((ks << 4) + nt0) * 64 + pb_ * 2];\
            bcur[0] = v.x; bcur[1] = v.y;                                     \
        }                                                                     \
        _Pragma("unroll")                                                     \
        for (int nt = 0; nt < 8; nt++) {                                      \
            if (nt < 7) {                                                     \
                int ntile = w_n * 8 + nt + 1;                                 \
                int pb_ = (lane + ntile) & 31;                                \
                uint2 v = *(const uint2*)&(BsB)[((ks << 4) + ntile) * 64 +    \
                                                pb_ * 2];                     \
                bnxt[0] = v.x; bnxt[1] = v.y;                                 \
            }                                                                 \
            mma_tf32(acc[0][nt], afr0, bcur);                                 \
            mma_tf32(acc[1][nt], afr1, bcur);                                 \
            bcur[0] = bnxt[0]; bcur[1] = bnxt[1];                             \
        }                                                                     \
    }

// ---------------- FFN GEMM 1: y = relu((h*a1+c1) @ f1w + f1b) ----------------
__global__ __launch_bounds__(256, 2) void ffn1_kernel(
    const float* __restrict__ h, const float* __restrict__ w,
    const float* __restrict__ bias) {
    extern __shared__ unsigned dsm[];
    unsigned* Abuf = dsm;          // [2][4096]
    unsigned* Bbuf = dsm + 8192;   // [2][4096]
    const int bm = blockIdx.y * 128;
    const int bn = blockIdx.x * 128;
    const int tid = threadIdx.x;
    const int lane = tid & 31, wid = tid >> 5;
    const int w_m = wid & 3, w_n = wid >> 2;
    const int g = lane >> 2, tg = lane & 3;
    const int ac4 = (tid & 7) << 2, arow0 = tid >> 3;
    const int bk0w = tid >> 5, bn4 = (tid & 31) << 2;

    float acc[2][8][4];
#pragma unroll
    for (int mt = 0; mt < 2; mt++)
#pragma unroll
        for (int nt = 0; nt < 8; nt++)
#pragma unroll
            for (int q = 0; q < 4; q++) acc[mt][nt][q] = 0.f;

    float4 pa[4], pb[4];
    STAGE_LOAD(pa, pb, h, DIM, w, HID, 0);
    STORE_A_AFF(Abuf, pa, 0);
    STORE_B(Bbuf, pb);
    __syncthreads();

#pragma unroll 1
    for (int kb = 0; kb < 16; kb++) {
        unsigned* Ac = Abuf + (kb & 1) * 4096;
        unsigned* Bc = Bbuf + (kb & 1) * 4096;
        if (kb < 15) { STAGE_LOAD(pa, pb, h, DIM, w, HID, (kb + 1) * 32); }
        COMPUTE_BLOCK(Ac, Bc);
        if (kb < 15) {
            unsigned* An = Abuf + ((kb + 1) & 1) * 4096;
            unsigned* Bn = Bbuf + ((kb + 1) & 1) * 4096;
            STORE_A_AFF(An, pa, (kb + 1) * 32);
            STORE_B(Bn, pb);
            __syncthreads();
        }
    }
    // ---- epilogue: bias + relu -> g_y ----
#pragma unroll
    for (int nt = 0; nt < 8; nt++) {
        int col = bn + w_n * 64 + nt * 8 + 2 * tg;
        float2 bv = *(const float2*)(bias + col);
#pragma unroll
        for (int mt = 0; mt < 2; mt++) {
            int r0 = bm + w_m * 32 + mt * 16 + g;
            float2 o0 = make_float2(fmaxf(acc[mt][nt][0] + bv.x, 0.f),
                                    fmaxf(acc[mt][nt][1] + bv.y, 0.f));
            float2 o1 = make_float2(fmaxf(acc[mt][nt][2] + bv.x, 0.f),
                                    fmaxf(acc[mt][nt][3] + bv.y, 0.f));
            *(float2*)(g_y + (size_t)r0 * HID + col) = o0;
            *(float2*)(g_y + (size_t)(r0 + 8) * HID + col) = o1;
        }
    }
}

// ---------------- FFN GEMM 2 + residual + bn2 ----------------
__global__ __launch_bounds__(256, 2) void ffn2_kernel(
    const float* __restrict__ h, const float* __restrict__ w,
    const float* __restrict__ bias, float* __restrict__ out) {
    extern __shared__ unsigned dsm[];
    unsigned* Abuf = dsm;
    unsigned* Bbuf = dsm + 8192;
    const int bm = blockIdx.y * 128;
    const int bn = blockIdx.x * 128;
    const int tid = threadIdx.x;
    const int lane = tid & 31, wid = tid >> 5;
    const int w_m = wid & 3, w_n = wid >> 2;
    const int g = lane >> 2, tg = lane & 3;
    const int ac4 = (tid & 7) << 2, arow0 = tid >> 3;
    const int bk0w = tid >> 5, bn4 = (tid & 31) << 2;

    float acc[2][8][4];
#pragma unroll
    for (int mt = 0; mt < 2; mt++)
#pragma unroll
        for (int nt = 0; nt < 8; nt++)
#pragma unroll
            for (int q = 0; q < 4; q++) acc[mt][nt][q] = 0.f;

    float4 pa[4], pb[4];
    STAGE_LOAD(pa, pb, g_y, HID, w, DIM, 0);
    STORE_A_PLAIN(Abuf, pa);
    STORE_B(Bbuf, pb);
    __syncthreads();

#pragma unroll 1
    for (int kb = 0; kb < 32; kb++) {
        unsigned* Ac = Abuf + (kb & 1) * 4096;
        unsigned* Bc = Bbuf + (kb & 1) * 4096;
        if (kb < 31) { STAGE_LOAD(pa, pb, g_y, HID, w, DIM, (kb + 1) * 32); }
        COMPUTE_BLOCK(Ac, Bc);
        if (kb < 31) {
            unsigned* An = Abuf + ((kb + 1) & 1) * 4096;
            unsigned* Bn = Bbuf + ((kb + 1) & 1) * 4096;
            STORE_A_PLAIN(An, pa);
            STORE_B(Bn, pb);
            __syncthreads();
        }
    }
    // ---- epilogue: residual (bn1-folded h) + f2b, then bn2 affine ----
#pragma unroll
    for (int nt = 0; nt < 8; nt++) {
        int col = bn + w_n * 64 + nt * 8 + 2 * tg;
        float2 fbv = *(const float2*)(bias + col);
        float2 a1v = *(const float2*)(g_a1 + col);
        float2 c1v = *(const float2*)(g_c1 + col);
        float2 a2v = *(const float2*)(g_a2 + col);
        float2 c2v = *(const float2*)(g_c2 + col);
#pragma unroll
        for (int mt = 0; mt < 2; mt++) {
            int r0 = bm + w_m * 32 + mt * 16 + g;
            float2 h0 = *(const float2*)(h + (size_t)r0 * DIM + col);
            float2 h1 = *(const float2*)(h + (size_t)(r0 + 8) * DIM + col);
            float2 o0, o1;
            o0.x = (fmaf(h0.x, a1v.x, c1v.x) + acc[mt][nt][0] + fbv.x) * a2v.x + c2v.x;
            o0.y = (fmaf(h0.y, a1v.y, c1v.y) + acc[mt][nt][1] + fbv.y) * a2v.y + c2v.y;
            o1.x = (fmaf(h1.x, a1v.x, c1v.x) + acc[mt][nt][2] + fbv.x) * a2v.x + c2v.x;
            o1.y = (fmaf(h1.y, a1v.y, c1v.y) + acc[mt][nt][3] + fbv.y) * a2v.y + c2v.y;
            *(float2*)(out + (size_t)r0 * DIM + col) = o0;
            *(float2*)(out + (size_t)(r0 + 8) * DIM + col) = o1;
        }
    }
}

extern "C" void kernel_launch(void* const* d_in, const int* in_sizes, int n_in,
                              void* d_out, int out_size) {
    // metadata order: A,h,qw,qb,kw,kb,vw,vb,ow,ob,f1w,f1b,f2w,f2b,bn1_*,bn2_*
    const float* h   = (const float*)d_in[1];
    const float* vw  = (const float*)d_in[6];
    const float* vb  = (const float*)d_in[7];
    const float* ow  = (const float*)d_in[8];
    const float* ob  = (const float*)d_in[9];
    const float* f1w = (const float*)d_in[10];
    const float* f1b = (const float*)d_in[11];
    const float* f2w = (const float*)d_in[12];
    const float* f2b = (const float*)d_in[13];
    const float* b1g = (const float*)d_in[14];
    const float* b1b = (const float*)d_in[15];
    const float* b1m = (const float*)d_in[16];
    const float* b1v = (const float*)d_in[17];
    const float* b2g = (const float*)d_in[18];
    const float* b2b = (const float*)d_in[19];
    const float* b2m = (const float*)d_in[20];
    const float* b2v = (const float*)d_in[21];
    float* out = (float*)d_out;

    // 64 KB dynamic smem per CTA (attribute set is idempotent, non-stream API)
    cudaFuncSetAttribute(ffn1_kernel, cudaFuncAttributeMaxDynamicSharedMemorySize, 65536);
    cudaFuncSetAttribute(ffn2_kernel, cudaFuncAttributeMaxDynamicSharedMemorySize, 65536);

    colsum_kernel<<<128, 512>>>(h);
    prep1_kernel<<<2, 256>>>(vw, vb);
    prep2_kernel<<<2, 256>>>(ow, ob, b1g, b1b, b1m, b1v, b2g, b2b, b2m, b2v);
    dim3 g1(HID / 128, NROWS / 128);   // (8, 64)
    ffn1_kernel<<<g1, 256, 65536>>>(h, f1w, f1b);
    dim3 g2(DIM / 128, NROWS / 128);   // (4, 64)
    ffn2_kernel<<<g2, 256, 65536>>>(h, f2w, f2b, out);
}

// round 8
// speedup vs baseline: 1.1117x; 1.1117x over previous
#include <cuda_runtime.h>

#define NROWS 8192
#define DIM   512
#define HID   1024

// Scratch (allocation-free: __device__ globals), all 16B-aligned.
__device__ __align__(16) float g_part[128 * DIM];
__device__ __align__(16) float g_s[DIM];
__device__ __align__(16) float g_a1[DIM], g_c1[DIM];
__device__ __align__(16) float g_a2[DIM], g_c2[DIM];
__device__ __align__(16) float g_y[(size_t)NROWS * HID];   // 32 MB

// ---------------- tf32 + mma helpers ----------------
__device__ __forceinline__ unsigned tf32r(float x) {
    unsigned r;
    asm("cvt.rna.tf32.f32 %0, %1;" : "=r"(r) : "f"(x));
    return r;
}
__device__ __forceinline__ void mma_tf32(float* d, const unsigned* a, const unsigned* b) {
    asm volatile(
        "mma.sync.aligned.m16n8k8.row.col.f32.tf32.tf32.f32 "
        "{%0,%1,%2,%3}, {%4,%5,%6,%7}, {%8,%9}, {%0,%1,%2,%3};"
        : "+f"(d[0]), "+f"(d[1]), "+f"(d[2]), "+f"(d[3])
        : "r"(a[0]), "r"(a[1]), "r"(a[2]), "r"(a[3]), "r"(b[0]), "r"(b[1]));
}

// ---------------- stage 1: column partial sums of h ----------------
__global__ void colsum_kernel(const float* __restrict__ h) {
    int d  = threadIdx.x;
    int r0 = blockIdx.x * 64;
    float s = 0.f;
#pragma unroll 8
    for (int r = 0; r < 64; r++)
        s += h[(size_t)(r0 + r) * DIM + d];
    g_part[blockIdx.x * DIM + d] = s;
}

// ---------------- stage 2: s = colsum(h)@vw + N*vb ----------------
__global__ void prep1_kernel(const float* __restrict__ vw,
                             const float* __restrict__ vb) {
    __shared__ float hs[DIM];
    for (int i = threadIdx.x; i < DIM; i += blockDim.x) {
        float s = 0.f;
#pragma unroll 8
        for (int b = 0; b < 128; b++) s += g_part[b * DIM + i];
        hs[i] = s;
    }
    __syncthreads();
    int d = blockIdx.x * blockDim.x + threadIdx.x;
    float s = 0.f;
#pragma unroll 8
    for (int k = 0; k < DIM; k++) s = fmaf(hs[k], vw[k * DIM + d], s);
    g_s[d] = s + 8192.0f * vb[d];
}

// ---------------- stage 3: t = s@ow+ob; fold bn affines ----------------
__global__ void prep2_kernel(const float* __restrict__ ow, const float* __restrict__ ob,
                             const float* __restrict__ g1, const float* __restrict__ b1,
                             const float* __restrict__ m1, const float* __restrict__ v1,
                             const float* __restrict__ g2, const float* __restrict__ b2,
                             const float* __restrict__ m2, const float* __restrict__ v2) {
    __shared__ float ss[DIM];
    for (int i = threadIdx.x; i < DIM; i += blockDim.x) ss[i] = g_s[i];
    __syncthreads();
    int d = blockIdx.x * blockDim.x + threadIdx.x;
    float t = 0.f;
#pragma unroll 8
    for (int k = 0; k < DIM; k++) t = fmaf(ss[k], ow[k * DIM + d], t);
    t += ob[d];
    float A1 = g1[d] * rsqrtf(v1[d] + 1e-5f);
    g_a1[d] = A1;
    g_c1[d] = (t - m1[d]) * A1 + b1[d];
    float A2 = g2[d] * rsqrtf(v2[d] + 1e-5f);
    g_a2[d] = A2;
    g_c2[d] = b2[d] - m2[d] * A2;
}

// =====================================================================
// ffn1: R4's double-buffered reg-prefetch kernel (VALIDATED in R4, 78.5us)
// Block 128x128, BK=32, 8 warps (4x2), warp 32x64. SMEM fragment-order.
// Dynamic smem: A[2][4096] u32 @ 0, B[2][4096] u32 @ 8192. 64 KB total.
// =====================================================================
#define STAGE_LOAD(pa, pb, Ap, ldA, Bp, ldB, k0)                              \
    _Pragma("unroll")                                                         \
    for (int i = 0; i < 4; i++)                                               \
        pa[i] = *(const float4*)(Ap + (size_t)(bm + arow0 + 32 * i) * ldA +   \
                                 (k0) + ac4);                                 \
    _Pragma("unroll")                                                         \
    for (int i = 0; i < 4; i++)                                               \
        pb[i] = *(const float4*)(Bp + (size_t)((k0) + bk0w + 8 * i) * ldB +   \
                                 bn + bn4);

#define STORE_A_AFF(dst, pa, k0)                                              \
    {                                                                         \
        const int kstep = ac4 >> 3;                                           \
        const int jhi = ((ac4 >> 2) & 1) << 1;                                \
        float4 av = *(const float4*)(g_a1 + (k0) + ac4);                      \
        float4 cv = *(const float4*)(g_c1 + (k0) + ac4);                      \
        _Pragma("unroll")                                                     \
        for (int i = 0; i < 4; i++) {                                         \
            int row = arow0 + 32 * i;                                         \
            int mtile = row >> 4, lane_r = (row & 7) << 2;                    \
            int j = jhi | ((row >> 3) & 1);                                   \
            float vals[4] = {fmaf(pa[i].x, av.x, cv.x),                       \
                             fmaf(pa[i].y, av.y, cv.y),                       \
                             fmaf(pa[i].z, av.z, cv.z),                       \
                             fmaf(pa[i].w, av.w, cv.w)};                      \
            unsigned* base = (dst) + ((kstep << 3) + mtile) * 128 + j;        \
            _Pragma("unroll")                                                 \
            for (int jj = 0; jj < 4; jj++)                                    \
                base[(((lane_r + jj + kstep) & 31) << 2)] = tf32r(vals[jj]);  \
        }                                                                     \
    }

#define STORE_B(dst, pb)                                                      \
    {                                                                         \
        const int jB = (bk0w >> 2) & 1;                                       \
        const int k3 = bk0w & 3;                                              \
        const int ntile = bn4 >> 3;                                           \
        const int lbase = (bn4 & 7) << 2;                                     \
        _Pragma("unroll")                                                     \
        for (int i = 0; i < 4; i++) {                                         \
            float vals[4] = {pb[i].x, pb[i].y, pb[i].z, pb[i].w};             \
            unsigned* base = (dst) + ((i << 4) + ntile) * 64 + jB;            \
            _Pragma("unroll")                                                 \
            for (int jj = 0; jj < 4; jj++) {                                  \
                int phys = ((lbase + (jj << 2)) | k3) + ntile;                \
                base[(phys & 31) << 1] = tf32r(vals[jj]);                     \
            }                                                                 \
        }                                                                     \
    }

#define COMPUTE_BLOCK(AsB, BsB)                                               \
    _Pragma("unroll")                                                         \
    for (int ks = 0; ks < 4; ks++) {                                          \
        unsigned afr0[4], afr1[4];                                            \
        int physa = (lane + ks) & 31;                                         \
        {                                                                     \
            uint4 v = *(const uint4*)&(AsB)[((ks << 3) + w_m * 2) * 128 +     \
                                            physa * 4];                       \
            afr0[0] = v.x; afr0[1] = v.y; afr0[2] = v.z; afr0[3] = v.w;       \
        }                                                                     \
        {                                                                     \
            uint4 v = *(const uint4*)&(AsB)[((ks << 3) + w_m * 2 + 1) * 128 + \
                                            physa * 4];                       \
            afr1[0] = v.x; afr1[1] = v.y; afr1[2] = v.z; afr1[3] = v.w;       \
        }                                                                     \
        unsigned bcur[2], bnxt[2];                                            \
        {                                                                     \
            int nt0 = w_n * 8;                                                \
            int pb_ = (lane + nt0) & 31;                                      \
            uint2 v = *(const uint2*)&(BsB)[((ks << 4) + nt0) * 64 + pb_ * 2];\
            bcur[0] = v.x; bcur[1] = v.y;                                     \
        }                                                                     \
        _Pragma("unroll")                                                     \
        for (int nt = 0; nt < 8; nt++) {                                      \
            if (nt < 7) {                                                     \
                int ntile = w_n * 8 + nt + 1;                                 \
                int pb_ = (lane + ntile) & 31;                                \
                uint2 v = *(const uint2*)&(BsB)[((ks << 4) + ntile) * 64 +    \
                                                pb_ * 2];                     \
                bnxt[0] = v.x; bnxt[1] = v.y;                                 \
            }                                                                 \
            mma_tf32(acc[0][nt], afr0, bcur);                                 \
            mma_tf32(acc[1][nt], afr1, bcur);                                 \
            bcur[0] = bnxt[0]; bcur[1] = bnxt[1];                             \
        }                                                                     \
    }

__global__ __launch_bounds__(256, 2) void ffn1_kernel(
    const float* __restrict__ h, const float* __restrict__ w,
    const float* __restrict__ bias) {
    extern __shared__ unsigned dsm[];
    unsigned* Abuf = dsm;          // [2][4096]
    unsigned* Bbuf = dsm + 8192;   // [2][4096]
    const int bm = blockIdx.y * 128;
    const int bn = blockIdx.x * 128;
    const int tid = threadIdx.x;
    const int lane = tid & 31, wid = tid >> 5;
    const int w_m = wid & 3, w_n = wid >> 2;
    const int g = lane >> 2, tg = lane & 3;
    const int ac4 = (tid & 7) << 2, arow0 = tid >> 3;
    const int bk0w = tid >> 5, bn4 = (tid & 31) << 2;

    float acc[2][8][4];
#pragma unroll
    for (int mt = 0; mt < 2; mt++)
#pragma unroll
        for (int nt = 0; nt < 8; nt++)
#pragma unroll
            for (int q = 0; q < 4; q++) acc[mt][nt][q] = 0.f;

    float4 pa[4], pb[4];
    STAGE_LOAD(pa, pb, h, DIM, w, HID, 0);
    STORE_A_AFF(Abuf, pa, 0);
    STORE_B(Bbuf, pb);
    __syncthreads();

#pragma unroll 1
    for (int kb = 0; kb < 16; kb++) {
        unsigned* Ac = Abuf + (kb & 1) * 4096;
        unsigned* Bc = Bbuf + (kb & 1) * 4096;
        if (kb < 15) { STAGE_LOAD(pa, pb, h, DIM, w, HID, (kb + 1) * 32); }
        COMPUTE_BLOCK(Ac, Bc);
        if (kb < 15) {
            unsigned* An = Abuf + ((kb + 1) & 1) * 4096;
            unsigned* Bn = Bbuf + ((kb + 1) & 1) * 4096;
            STORE_A_AFF(An, pa, (kb + 1) * 32);
            STORE_B(Bn, pb);
            __syncthreads();
        }
    }
    // ---- epilogue: bias + relu -> g_y ----
#pragma unroll
    for (int nt = 0; nt < 8; nt++) {
        int col = bn + w_n * 64 + nt * 8 + 2 * tg;
        float2 bv = *(const float2*)(bias + col);
#pragma unroll
        for (int mt = 0; mt < 2; mt++) {
            int r0 = bm + w_m * 32 + mt * 16 + g;
            float2 o0 = make_float2(fmaxf(acc[mt][nt][0] + bv.x, 0.f),
                                    fmaxf(acc[mt][nt][1] + bv.y, 0.f));
            float2 o1 = make_float2(fmaxf(acc[mt][nt][2] + bv.x, 0.f),
                                    fmaxf(acc[mt][nt][3] + bv.y, 0.f));
            *(float2*)(g_y + (size_t)r0 * HID + col) = o0;
            *(float2*)(g_y + (size_t)(r0 + 8) * HID + col) = o1;
        }
    }
}

// =====================================================================
// ffn2: R3's single-buffered kernel (VALIDATED in R3), static smem.
// out = ((h*a1+c1) + y@f2w + f2b) * a2 + c2.  M=8192, K=1024, N=512.
// =====================================================================
__global__ __launch_bounds__(256, 2) void ffn2_kernel(
    const float* __restrict__ h, const float* __restrict__ w,
    const float* __restrict__ bias, float* __restrict__ out) {
    __shared__ __align__(16) unsigned As[4096];
    __shared__ __align__(16) unsigned Bs[4096];
    const int bm = blockIdx.y * 128;
    const int bn = blockIdx.x * 128;
    const int tid = threadIdx.x;
    const int lane = tid & 31, wid = tid >> 5;
    const int w_m = wid & 3, w_n = wid >> 2;
    const int g = lane >> 2, tg = lane & 3;

    float acc[2][8][4];
#pragma unroll
    for (int mt = 0; mt < 2; mt++)
#pragma unroll
        for (int nt = 0; nt < 8; nt++)
#pragma unroll
            for (int q = 0; q < 4; q++) acc[mt][nt][q] = 0.f;

    for (int k0 = 0; k0 < HID; k0 += 32) {
        // ---- stage A from g_y ----
#pragma unroll
        for (int i = 0; i < 4; i++) {
            int fidx = tid + i * 256;
            int row = fidx >> 3;
            int c4  = (fidx & 7) << 2;
            float4 yv = *(const float4*)(g_y + (size_t)(bm + row) * HID + k0 + c4);
            float vals[4] = {yv.x, yv.y, yv.z, yv.w};
            int mtile = row >> 4;
            int lane_r = (row & 7) << 2;
            int jb0 = (row >> 3) & 1;
#pragma unroll
            for (int jj = 0; jj < 4; jj++) {
                int cc = c4 + jj;
                int kstep = cc >> 3;
                int l = lane_r | (cc & 3);
                int phys = (l + kstep) & 31;
                int j = (((cc >> 2) & 1) << 1) | jb0;
                As[((kstep << 3) + mtile) * 128 + phys * 4 + j] = tf32r(vals[jj]);
            }
        }
        // ---- stage B ----
#pragma unroll
        for (int i = 0; i < 4; i++) {
            int fidx = tid + i * 256;
            int k  = fidx >> 5;
            int n4 = (fidx & 31) << 2;
            float4 wv = *(const float4*)(w + (size_t)(k0 + k) * DIM + bn + n4);
            float vals[4] = {wv.x, wv.y, wv.z, wv.w};
            int kstep = k >> 3;
            int j = (k >> 2) & 1;
            int k3 = k & 3;
#pragma unroll
            for (int jj = 0; jj < 4; jj++) {
                int n = n4 + jj;
                int ntile = n >> 3;
                int l = ((n & 7) << 2) | k3;
                int phys = (l + ntile) & 31;
                Bs[((kstep << 4) + ntile) * 64 + phys * 2 + j] = tf32r(vals[jj]);
            }
        }
        __syncthreads();
#pragma unroll
        for (int ks = 0; ks < 4; ks++) {
            unsigned afr[2][4], bfr[8][2];
            int physa = (lane + ks) & 31;
#pragma unroll
            for (int mt = 0; mt < 2; mt++) {
                int mtile = w_m * 2 + mt;
                uint4 v = *(const uint4*)&As[((ks << 3) + mtile) * 128 + physa * 4];
                afr[mt][0] = v.x; afr[mt][1] = v.y; afr[mt][2] = v.z; afr[mt][3] = v.w;
            }
#pragma unroll
            for (int nt = 0; nt < 8; nt++) {
                int ntile = w_n * 8 + nt;
                int physb = (lane + ntile) & 31;
                uint2 v = *(const uint2*)&Bs[((ks << 4) + ntile) * 64 + physb * 2];
                bfr[nt][0] = v.x; bfr[nt][1] = v.y;
            }
#pragma unroll
            for (int mt = 0; mt < 2; mt++)
#pragma unroll
                for (int nt = 0; nt < 8; nt++)
                    mma_tf32(acc[mt][nt], afr[mt], bfr[nt]);
        }
        __syncthreads();
    }
    // ---- epilogue: residual (bn1-folded h) + f2b, then bn2 affine ----
#pragma unroll
    for (int nt = 0; nt < 8; nt++) {
        int col = bn + w_n * 64 + nt * 8 + 2 * tg;
        float2 fbv = *(const float2*)(bias + col);
        float2 a1v = *(const float2*)(g_a1 + col);
        float2 c1v = *(const float2*)(g_c1 + col);
        float2 a2v = *(const float2*)(g_a2 + col);
        float2 c2v = *(const float2*)(g_c2 + col);
#pragma unroll
        for (int mt = 0; mt < 2; mt++) {
            int r0 = bm + w_m * 32 + mt * 16 + g;
            float2 h0 = *(const float2*)(h + (size_t)r0 * DIM + col);
            float2 h1 = *(const float2*)(h + (size_t)(r0 + 8) * DIM + col);
            float2 o0, o1;
            o0.x = (fmaf(h0.x, a1v.x, c1v.x) + acc[mt][nt][0] + fbv.x) * a2v.x + c2v.x;
            o0.y = (fmaf(h0.y, a1v.y, c1v.y) + acc[mt][nt][1] + fbv.y) * a2v.y + c2v.y;
            o1.x = (fmaf(h1.x, a1v.x, c1v.x) + acc[mt][nt][2] + fbv.x) * a2v.x + c2v.x;
            o1.y = (fmaf(h1.y, a1v.y, c1v.y) + acc[mt][nt][3] + fbv.y) * a2v.y + c2v.y;
            *(float2*)(out + (size_t)r0 * DIM + col) = o0;
            *(float2*)(out + (size_t)(r0 + 8) * DIM + col) = o1;
        }
    }
}

extern "C" void kernel_launch(void* const* d_in, const int* in_sizes, int n_in,
                              void* d_out, int out_size) {
    // metadata order: A,h,qw,qb,kw,kb,vw,vb,ow,ob,f1w,f1b,f2w,f2b,bn1_*,bn2_*
    const float* h   = (const float*)d_in[1];
    const float* vw  = (const float*)d_in[6];
    const float* vb  = (const float*)d_in[7];
    const float* ow  = (const float*)d_in[8];
    const float* ob  = (const float*)d_in[9];
    const float* f1w = (const float*)d_in[10];
    const float* f1b = (const float*)d_in[11];
    const float* f2w = (const float*)d_in[12];
    const float* f2b = (const float*)d_in[13];
    const float* b1g = (const float*)d_in[14];
    const float* b1b = (const float*)d_in[15];
    const float* b1m = (const float*)d_in[16];
    const float* b1v = (const float*)d_in[17];
    const float* b2g = (const float*)d_in[18];
    const float* b2b = (const float*)d_in[19];
    const float* b2m = (const float*)d_in[20];
    const float* b2v = (const float*)d_in[21];
    float* out = (float*)d_out;

    cudaFuncSetAttribute(ffn1_kernel, cudaFuncAttributeMaxDynamicSharedMemorySize, 65536);

    colsum_kernel<<<128, 512>>>(h);
    prep1_kernel<<<2, 256>>>(vw, vb);
    prep2_kernel<<<2, 256>>>(ow, ob, b1g, b1b, b1m, b1v, b2g, b2b, b2m, b2v);
    dim3 g1(HID / 128, NROWS / 128);   // (8, 64)
    ffn1_kernel<<<g1, 256, 65536>>>(h, f1w, f1b);
    dim3 g2(DIM / 128, NROWS / 128);   // (4, 64)
    ffn2_kernel<<<g2, 256>>>(h, f2w, f2b, out);
}